// round 3
// baseline (speedup 1.0000x reference)
#include <cuda_runtime.h>

#define BB   8
#define NN   2048
#define KK   32
#define DD   64
#define CC1  64
#define CC2  128
#define NPTS (BB*NN)          // 16384
#define ROWS (BB*NN*KK)       // 524288
#define R2f  0.0225f
#define EPSd 1e-5
#define NB1  128              // k_stats1 blocks
#define NB2  592              // k_main blocks

// ---------------- device scratch (no allocations allowed) ----------------
__device__ int    g_idx[ROWS];              // 2 MB   neighbor indices
__device__ float  g_F1[NPTS*CC1];           // 4 MB   feature @ W1[3:]
__device__ double g_p1s[NB1][CC1];          // BN1 per-block partial sums
__device__ double g_p1q[NB1][CC1];
__device__ double g_p2s[NB2][CC2];          // BN2 per-block partial sums
__device__ double g_p2q[NB2][CC2];
__device__ float  g_a1[CC1], g_b1c[CC1];    // BN1 affine
__device__ float  g_a2[CC2], g_b2c[CC2];    // BN2 affine
__device__ float  g_mx[NPTS*CC2];           // 8 MB   max_k z (pre-BN2)
__device__ float  g_mn[NPTS*CC2];           // 8 MB   min_k z (a2<0 safety)

// ---------------- f32x2 packed helpers ----------------
__device__ __forceinline__ unsigned long long pack2(float v) {
    unsigned long long d;
    asm("mov.b64 %0, {%1, %1};" : "=l"(d) : "r"(__float_as_uint(v)));
    return d;
}
__device__ __forceinline__ void fma2(unsigned long long& acc,
                                     unsigned long long a, unsigned long long b) {
    asm("fma.rn.f32x2 %0, %1, %2, %0;" : "+l"(acc) : "l"(a), "l"(b));
}
__device__ __forceinline__ float2 unpack2(unsigned long long v) {
    float2 r;
    asm("mov.b64 {%0, %1}, %2;" : "=f"(r.x), "=f"(r.y) : "l"(v));
    return r;
}

// ---------------- K0: ball query (first 32 ascending in-radius) ----------------
__global__ void k_ball(const float* __restrict__ pos) {
    __shared__ float4 sp[NN];                    // 32 KB (x,y,z,|x|^2)
    int b    = blockIdx.x >> 4;                  // 16 tiles of 128 per batch
    int tile = blockIdx.x & 15;
    const float* pb = pos + b*NN*3;
    for (int j = threadIdx.x; j < NN; j += 128) {
        float x = pb[3*j], y = pb[3*j+1], z = pb[3*j+2];
        sp[j] = make_float4(x, y, z, x*x + y*y + z*z);
    }
    __syncthreads();
    int i = tile*128 + threadIdx.x;
    float4 pi = sp[i];
    int base = (b*NN + i)*KK;
    int cnt = 0, first = 0;
    for (int j = 0; j < NN; ++j) {
        float4 pj = sp[j];
        float sq = pi.w + pj.w - 2.f*(pi.x*pj.x + pi.y*pj.y + pi.z*pj.z);
        if (!(sq > R2f)) {
            if (cnt == 0) first = j;
            g_idx[base + cnt] = j;
            if (++cnt == KK) break;
        }
    }
    for (; cnt < KK; ++cnt) g_idx[base + cnt] = first;
}

// ---------------- K1: F1 = feature @ W1[3:,:] ----------------
__global__ void k_f1(const float* __restrict__ feat, const float* __restrict__ W1) {
    __shared__ float Ws[DD*CC1];                 // 16 KB
    for (int t = threadIdx.x; t < DD*CC1; t += blockDim.x)
        Ws[t] = W1[3*CC1 + t];
    __syncthreads();
    int row = blockIdx.x*blockDim.x + threadIdx.x;
    if (row >= NPTS) return;
    const float4* f4 = (const float4*)(feat + row*DD);
    float acc[CC1];
    #pragma unroll
    for (int c = 0; c < CC1; ++c) acc[c] = 0.f;
    for (int k4 = 0; k4 < DD/4; ++k4) {
        float4 fv = f4[k4];
        const float* w = Ws + (k4*4)*CC1;
        #pragma unroll
        for (int c = 0; c < CC1; ++c) {
            acc[c] = fmaf(fv.x, w[c],        acc[c]);
            acc[c] = fmaf(fv.y, w[CC1+c],    acc[c]);
            acc[c] = fmaf(fv.z, w[2*CC1+c],  acc[c]);
            acc[c] = fmaf(fv.w, w[3*CC1+c],  acc[c]);
        }
    }
    float4* o = (float4*)(g_F1 + row*CC1);
    #pragma unroll
    for (int c = 0; c < CC1/4; ++c)
        o[c] = make_float4(acc[4*c], acc[4*c+1], acc[4*c+2], acc[4*c+3]);
}

// ---------------- K2: BN1 channel partial sums (deterministic slots) ----------------
__global__ void k_stats1(const float* __restrict__ pos, const float* __restrict__ W1) {
    int t = threadIdx.x;
    int c = t & 63;
    float w0 = W1[c], w1 = W1[CC1 + c], w2 = W1[2*CC1 + c];
    int grp  = (blockIdx.x*blockDim.x + t) >> 6;
    int ngrp = (NB1*256) >> 6;                 // 512 groups
    float s = 0.f, q = 0.f;
    for (int r = grp; r < ROWS; r += ngrp) {
        int p  = r >> 5;                       // point index b*N+i
        int j  = g_idx[r];
        int bj = (p & ~(NN-1)) + j;
        const float* pj = pos + bj*3;
        const float* pi = pos + p*3;
        float dx = pj[0]-pi[0], dy = pj[1]-pi[1], dz = pj[2]-pi[2];
        float h = g_F1[bj*CC1 + c] + dx*w0 + dy*w1 + dz*w2;
        s += h;
        q = fmaf(h, h, q);
    }
    __shared__ float ss[256], qs[256];
    ss[t] = s; qs[t] = q;
    __syncthreads();
    if (t < 64) {
        double S = (double)ss[t] + ss[t+64] + ss[t+128] + ss[t+192];
        double Q = (double)qs[t] + qs[t+64] + qs[t+128] + qs[t+192];
        g_p1s[blockIdx.x][t] = S;
        g_p1q[blockIdx.x][t] = Q;
    }
}

__global__ void k_fin1(const float* __restrict__ gm, const float* __restrict__ bt) {
    int c = threadIdx.x;           // 64 threads
    double S = 0.0, Q = 0.0;
    for (int b = 0; b < NB1; ++b) { S += g_p1s[b][c]; Q += g_p1q[b][c]; }
    double mean = S / (double)ROWS;
    double var  = Q / (double)ROWS - mean*mean;
    float a = gm[c] * rsqrtf((float)(var + EPSd));
    g_a1[c]  = a;
    g_b1c[c] = bt[c] - (float)mean * a;
}

// ---------------- K3: main fused kernel ----------------
// per point: y1[32x64] = relu(bn1(F1[j] + dx@W1xyz)); z = y1 @ W2 (f32x2 SIMT GEMM);
// track max_k / min_k z, accumulate BN2 partial sums.
__global__ void __launch_bounds__(128)
k_main(const float* __restrict__ pos, const float* __restrict__ W1,
       const float* __restrict__ W2) {
    __shared__ __align__(16) float W2s[CC1*CC2];   // 32 KB, [kk][c]
    __shared__ __align__(16) float yT[CC1][KK];    // 8 KB,  [c1][k]
    __shared__ float  w1x[3*CC1];
    __shared__ float  a1s[CC1], b1s[CC1];
    __shared__ int    idxs[KK];
    __shared__ float4 dxs[KK];
    __shared__ float  redmx[4][CC2];
    __shared__ float  redmn[4][CC2];

    int t = threadIdx.x;
    int lane = t & 31, warp = t >> 5;
    for (int u = t; u < CC1*CC2; u += 128) W2s[u] = W2[u];
    for (int u = t; u < 3*CC1;   u += 128) w1x[u] = W1[u];   // FIXED: was if(t<192)
    if (t < CC1)  { a1s[t] = g_a1[t]; b1s[t] = g_b1c[t]; }
    __syncthreads();

    int c0 = lane*4;    // channel quad
    int k0 = warp*8;    // neighbor octet
    float zs[4] = {0,0,0,0};   // BN2 partial sums (per owned channel)
    float zq[4] = {0,0,0,0};

    int kA  = t & 31;       // phase-B: this thread's neighbor
    int cAb = t >> 5;       // phase-B: base channel (c = cAb + 4s)

    for (int p = blockIdx.x; p < NPTS; p += gridDim.x) {
        __syncthreads();   // protect smem reuse across loop iterations
        // phase A: fetch neighbor idx + dx
        if (t < KK) {
            int j = g_idx[p*KK + t];
            idxs[t] = j;
            int bj = (p & ~(NN-1)) + j;
            const float* pj = pos + bj*3;
            const float* pi = pos + p*3;
            dxs[t] = make_float4(pj[0]-pi[0], pj[1]-pi[1], pj[2]-pi[2], 0.f);
        }
        __syncthreads();
        // phase B: y1 (transposed store, conflict-free)
        {
            int j = idxs[kA];
            float4 dv = dxs[kA];
            const float* f1p = g_F1 + ((p & ~(NN-1)) + j)*CC1;
            #pragma unroll
            for (int s = 0; s < 16; ++s) {
                int c = cAb + 4*s;
                float h = f1p[c] + dv.x*w1x[c] + dv.y*w1x[CC1+c] + dv.z*w1x[2*CC1+c];
                yT[c][kA] = fmaxf(fmaf(a1s[c], h, b1s[c]), 0.f);
            }
        }
        __syncthreads();
        // phase C: z tile GEMM, f32x2 packed (pairs along k)
        unsigned long long acc[16];
        #pragma unroll
        for (int u = 0; u < 16; ++u) acc[u] = 0ULL;
        #pragma unroll 8
        for (int kk = 0; kk < CC1; ++kk) {
            ulonglong2 ya = *(const ulonglong2*)&yT[kk][k0];     // k0..k0+3
            ulonglong2 yb = *(const ulonglong2*)&yT[kk][k0+4];   // k0+4..k0+7
            float4 wq = *(const float4*)(W2s + kk*CC2 + c0);
            unsigned long long w0p = pack2(wq.x), w1p = pack2(wq.y);
            unsigned long long w2p = pack2(wq.z), w3p = pack2(wq.w);
            fma2(acc[0],  ya.x, w0p); fma2(acc[1],  ya.y, w0p);
            fma2(acc[2],  yb.x, w0p); fma2(acc[3],  yb.y, w0p);
            fma2(acc[4],  ya.x, w1p); fma2(acc[5],  ya.y, w1p);
            fma2(acc[6],  yb.x, w1p); fma2(acc[7],  yb.y, w1p);
            fma2(acc[8],  ya.x, w2p); fma2(acc[9],  ya.y, w2p);
            fma2(acc[10], yb.x, w2p); fma2(acc[11], yb.y, w2p);
            fma2(acc[12], ya.x, w3p); fma2(acc[13], ya.y, w3p);
            fma2(acc[14], yb.x, w3p); fma2(acc[15], yb.y, w3p);
        }
        // per-thread reduce over its 8 k rows
        #pragma unroll
        for (int cl = 0; cl < 4; ++cl) {
            float mx = -3.4e38f, mn = 3.4e38f, sz = 0.f, sq = 0.f;
            #pragma unroll
            for (int kp = 0; kp < 4; ++kp) {
                float2 v = unpack2(acc[cl*4 + kp]);
                mx = fmaxf(mx, fmaxf(v.x, v.y));
                mn = fminf(mn, fminf(v.x, v.y));
                sz += v.x + v.y;
                sq = fmaf(v.x, v.x, fmaf(v.y, v.y, sq));
            }
            zs[cl] += sz; zq[cl] += sq;
            redmx[warp][c0+cl] = mx;
            redmn[warp][c0+cl] = mn;
        }
        __syncthreads();
        // cross-warp max/min, write scratch (128 threads == 128 channels)
        {
            int c = t;
            float m0 = fmaxf(fmaxf(redmx[0][c], redmx[1][c]),
                             fmaxf(redmx[2][c], redmx[3][c]));
            float n0 = fminf(fminf(redmn[0][c], redmn[1][c]),
                             fminf(redmn[2][c], redmn[3][c]));
            g_mx[p*CC2 + c] = m0;
            g_mn[p*CC2 + c] = n0;
        }
    }
    // BN2 partials: combine across warps, deterministic per-block slot
    __syncthreads();
    #pragma unroll
    for (int cl = 0; cl < 4; ++cl) {
        redmx[warp][c0+cl] = zs[cl];
        redmn[warp][c0+cl] = zq[cl];
    }
    __syncthreads();
    if (t < CC2) {
        double S = (double)redmx[0][t] + redmx[1][t] + redmx[2][t] + redmx[3][t];
        double Q = (double)redmn[0][t] + redmn[1][t] + redmn[2][t] + redmn[3][t];
        g_p2s[blockIdx.x][t] = S;
        g_p2q[blockIdx.x][t] = Q;
    }
}

__global__ void k_fin2(const float* __restrict__ gm, const float* __restrict__ bt) {
    int c = threadIdx.x;          // 128 threads
    double S = 0.0, Q = 0.0;
    for (int b = 0; b < NB2; ++b) { S += g_p2s[b][c]; Q += g_p2q[b][c]; }
    double mean = S / (double)ROWS;
    double var  = Q / (double)ROWS - mean*mean;
    float a = gm[c] * rsqrtf((float)(var + EPSd));
    g_a2[c]  = a;
    g_b2c[c] = bt[c] - (float)mean * a;
}

// ---------------- K4: epilogue — bn2 + relu on max (min if a2<0) ----------------
__global__ void k_out(float* __restrict__ out) {
    int idx = blockIdx.x*blockDim.x + threadIdx.x;
    if (idx >= NPTS*CC2) return;
    int c = idx & (CC2-1);
    float a = g_a2[c], b = g_b2c[c];
    float v = (a >= 0.f) ? g_mx[idx] : g_mn[idx];
    out[idx] = fmaxf(fmaf(a, v, b), 0.f);
}

// ---------------- launch ----------------
extern "C" void kernel_launch(void* const* d_in, const int* in_sizes, int n_in,
                              void* d_out, int out_size) {
    (void)in_sizes; (void)n_in; (void)out_size;
    const float* pos  = (const float*)d_in[0];
    const float* feat = (const float*)d_in[1];
    const float* W1   = (const float*)d_in[2];
    const float* g1   = (const float*)d_in[3];
    const float* b1   = (const float*)d_in[4];
    const float* W2   = (const float*)d_in[5];
    const float* g2   = (const float*)d_in[6];
    const float* b2   = (const float*)d_in[7];
    float* out = (float*)d_out;

    // output layout: [position | new_feature]
    cudaMemcpyAsync(out, pos, (size_t)BB*NN*3*sizeof(float),
                    cudaMemcpyDeviceToDevice);

    k_ball  <<<BB*(NN/128), 128>>>(pos);
    k_f1    <<<NPTS/128, 128>>>(feat, W1);
    k_stats1<<<NB1, 256>>>(pos, W1);
    k_fin1  <<<1, CC1>>>(g1, b1);
    k_main  <<<NB2, 128>>>(pos, W1, W2);
    k_fin2  <<<1, CC2>>>(g2, b2);
    k_out   <<<(NPTS*CC2)/256, 256>>>(out + BB*NN*3);
}

// round 8
// speedup vs baseline: 1.3805x; 1.3805x over previous
#include <cuda_runtime.h>

#define BB   8
#define NN   2048
#define KK   32
#define DD   64
#define CC1  64
#define CC2  128
#define NPTS (BB*NN)          // 16384
#define ROWS (BB*NN*KK)       // 524288
#define R2f  0.0225f
#define EPSd 1e-5
#define NB1  128              // k_stats1 blocks
#define NB2  592              // k_main blocks (4 per SM)

// ---------------- device scratch ----------------
__device__ int    g_idx[ROWS];              // 2 MB
__device__ float  g_G[NPTS*CC1];            // 4 MB  F1 + pos@W1xyz
__device__ float  g_P[NPTS*CC1];            // 4 MB  pos@W1xyz
__device__ double g_p1s[NB1][CC1];
__device__ double g_p1q[NB1][CC1];
__device__ double g_p2s[NB2][CC2];
__device__ double g_p2q[NB2][CC2];
__device__ float  g_a1[CC1], g_b1c[CC1];
__device__ float  g_a2[CC2], g_b2c[CC2];
__device__ float  g_mx[NPTS*CC2];           // 8 MB
__device__ float  g_mn[NPTS*CC2];           // 8 MB

// ---------------- f32x2 helpers ----------------
__device__ __forceinline__ unsigned long long pack2(float v) {
    unsigned long long d;
    asm("mov.b64 %0, {%1, %1};" : "=l"(d) : "r"(__float_as_uint(v)));
    return d;
}
__device__ __forceinline__ void fma2(unsigned long long& acc,
                                     unsigned long long a, unsigned long long b) {
    asm("fma.rn.f32x2 %0, %1, %2, %0;" : "+l"(acc) : "l"(a), "l"(b));
}
__device__ __forceinline__ float2 unpack2(unsigned long long v) {
    float2 r;
    asm("mov.b64 {%0, %1}, %2;" : "=f"(r.x), "=f"(r.y) : "l"(v));
    return r;
}

// ---------------- K0: ball query ----------------
__global__ void k_ball(const float* __restrict__ pos) {
    __shared__ float4 sp[NN];
    int b    = blockIdx.x >> 4;
    int tile = blockIdx.x & 15;
    const float* pb = pos + b*NN*3;
    for (int j = threadIdx.x; j < NN; j += 128) {
        float x = pb[3*j], y = pb[3*j+1], z = pb[3*j+2];
        sp[j] = make_float4(x, y, z, x*x + y*y + z*z);
    }
    __syncthreads();
    int i = tile*128 + threadIdx.x;
    float4 pi = sp[i];
    int base = (b*NN + i)*KK;
    int cnt = 0, first = 0;
    for (int j = 0; j < NN; ++j) {
        float4 pj = sp[j];
        float sq = pi.w + pj.w - 2.f*(pi.x*pj.x + pi.y*pj.y + pi.z*pj.z);
        if (!(sq > R2f)) {
            if (cnt == 0) first = j;
            g_idx[base + cnt] = j;
            if (++cnt == KK) break;
        }
    }
    for (; cnt < KK; ++cnt) g_idx[base + cnt] = first;
}

// ---------------- K1: G = F1 + pos@W1xyz,  P = pos@W1xyz ----------------
__global__ void k_f1(const float* __restrict__ pos, const float* __restrict__ feat,
                     const float* __restrict__ W1) {
    __shared__ float Ws[DD*CC1];                 // 16 KB (rows 3..66)
    __shared__ float w1s[3*CC1];
    for (int t = threadIdx.x; t < DD*CC1; t += blockDim.x) Ws[t] = W1[3*CC1 + t];
    for (int t = threadIdx.x; t < 3*CC1;  t += blockDim.x) w1s[t] = W1[t];
    __syncthreads();
    int row = blockIdx.x*blockDim.x + threadIdx.x;
    if (row >= NPTS) return;
    const float4* f4 = (const float4*)(feat + row*DD);
    float acc[CC1];
    #pragma unroll
    for (int c = 0; c < CC1; ++c) acc[c] = 0.f;
    for (int k4 = 0; k4 < DD/4; ++k4) {
        float4 fv = f4[k4];
        const float* w = Ws + (k4*4)*CC1;
        #pragma unroll
        for (int c = 0; c < CC1; ++c) {
            acc[c] = fmaf(fv.x, w[c],        acc[c]);
            acc[c] = fmaf(fv.y, w[CC1+c],    acc[c]);
            acc[c] = fmaf(fv.z, w[2*CC1+c],  acc[c]);
            acc[c] = fmaf(fv.w, w[3*CC1+c],  acc[c]);
        }
    }
    float px = pos[row*3], py = pos[row*3+1], pz = pos[row*3+2];
    float4* oG = (float4*)(g_G + row*CC1);
    float4* oP = (float4*)(g_P + row*CC1);
    #pragma unroll
    for (int c4 = 0; c4 < CC1/4; ++c4) {
        float4 pv, gv;
        float* pvp = &pv.x; float* gvp = &gv.x;
        #pragma unroll
        for (int v = 0; v < 4; ++v) {
            int c = c4*4 + v;
            float P = fmaf(px, w1s[c], fmaf(py, w1s[CC1+c], pz*w1s[2*CC1+c]));
            pvp[v] = P;
            gvp[v] = acc[c] + P;
        }
        oP[c4] = pv;
        oG[c4] = gv;
    }
}

// ---------------- K2: BN1 partial sums:  h = G[j] - P[i] ----------------
__global__ void k_stats1() {
    int t = threadIdx.x;
    int c = t & 63;
    int grp  = (blockIdx.x*blockDim.x + t) >> 6;
    int ngrp = (NB1*256) >> 6;                 // 512
    float s = 0.f, q = 0.f;
    for (int r = grp; r < ROWS; r += ngrp) {
        int p  = r >> 5;
        int j  = g_idx[r];
        int bj = (p & ~(NN-1)) + j;
        float h = g_G[bj*CC1 + c] - g_P[p*CC1 + c];
        s += h;
        q = fmaf(h, h, q);
    }
    __shared__ float ss[256], qs[256];
    ss[t] = s; qs[t] = q;
    __syncthreads();
    if (t < 64) {
        g_p1s[blockIdx.x][t] = (double)ss[t] + ss[t+64] + ss[t+128] + ss[t+192];
        g_p1q[blockIdx.x][t] = (double)qs[t] + qs[t+64] + qs[t+128] + qs[t+192];
    }
}

// ---------------- K2b: finalize BN1 (parallel over slots) ----------------
__global__ void k_fin1(const float* __restrict__ gm, const float* __restrict__ bt) {
    __shared__ double shs[512], shq[512];
    int t = threadIdx.x;                // 512 threads: c = t&63, s = t>>6 (0..7)
    int c = t & 63, s = t >> 6;
    double S = 0.0, Q = 0.0;
    for (int b = s; b < NB1; b += 8) { S += g_p1s[b][c]; Q += g_p1q[b][c]; }
    shs[t] = S; shq[t] = Q;
    __syncthreads();
    if (t < 64) {
        S = 0.0; Q = 0.0;
        #pragma unroll
        for (int k = 0; k < 8; ++k) { S += shs[k*64 + t]; Q += shq[k*64 + t]; }
        double mean = S / (double)ROWS;
        double var  = Q / (double)ROWS - mean*mean;
        float a = gm[t] * rsqrtf((float)(var + EPSd));
        g_a1[t]  = a;
        g_b1c[t] = bt[t] - (float)mean * a;
    }
}

// ---------------- K3: main fused kernel ----------------
__global__ void __launch_bounds__(128, 4)
k_main(const float* __restrict__ W2) {
    __shared__ __align__(16) float W2s[CC1*CC2];   // 32 KB [kk][c]
    __shared__ __align__(16) float yT[CC1][KK];    // 8 KB  [c][k^8q]
    __shared__ __align__(16) float a1s[CC1], b1s[CC1], bets[CC1];
    __shared__ int idxs[KK];

    int t = threadIdx.x;
    int lane = t & 31, w = t >> 5;
    for (int u = t; u < CC1*CC2; u += 128) W2s[u] = W2[u];
    if (t < CC1) { a1s[t] = g_a1[t]; b1s[t] = g_b1c[t]; }

    // phase-B mapping
    int kB = t >> 2, qB = t & 3;
    int ksB = kB ^ (qB << 3);          // conflict-free skewed column
    // phase-C mapping: warp owns channels w*32..w*32+31, thread 4ch x 8k
    int cg = lane >> 2, kg = lane & 3;
    int cBase = w*32 + cg*4;
    float zs[4] = {0,0,0,0}, zq[4] = {0,0,0,0};

    for (int p = blockIdx.x; p < NPTS; p += gridDim.x) {
        __syncthreads();               // yT/bets consumed by previous iter
        // phase A
        if (t < KK) idxs[t] = g_idx[p*KK + t];
        if (t < CC1) bets[t] = b1s[t] - a1s[t]*g_P[p*CC1 + t];
        __syncthreads();
        // phase B: coalesced gather + bn1 + relu, skewed transpose store
        {
            int j = idxs[kB];
            const float4* gr = (const float4*)(g_G + ((p & ~(NN-1)) + j)*CC1);
            #pragma unroll
            for (int u = 0; u < 4; ++u) {
                int ch = u*4 + qB;                 // 16B chunk index
                float4 gv = gr[ch];
                float4 av = ((const float4*)a1s)[ch];
                float4 bv = ((const float4*)bets)[ch];
                int c0 = ch*4;
                yT[c0+0][ksB] = fmaxf(fmaf(av.x, gv.x, bv.x), 0.f);
                yT[c0+1][ksB] = fmaxf(fmaf(av.y, gv.y, bv.y), 0.f);
                yT[c0+2][ksB] = fmaxf(fmaf(av.z, gv.z, bv.z), 0.f);
                yT[c0+3][ksB] = fmaxf(fmaf(av.w, gv.w, bv.w), 0.f);
            }
        }
        __syncthreads();
        // phase C: z = y1 @ W2 tile, f32x2
        unsigned long long acc[16];
        #pragma unroll
        for (int u = 0; u < 16; ++u) acc[u] = 0ULL;
        #pragma unroll 8
        for (int kk = 0; kk < CC1; ++kk) {
            int qc = (kk >> 2) & 3;
            const float* yrow = &yT[kk][(kg ^ qc) << 3];
            ulonglong2 ya = *(const ulonglong2*)yrow;        // k+0..3
            ulonglong2 yb = *(const ulonglong2*)(yrow + 4);  // k+4..7
            float4 wq = *(const float4*)&W2s[kk*CC2 + cBase];
            unsigned long long w0p = pack2(wq.x), w1p = pack2(wq.y);
            unsigned long long w2p = pack2(wq.z), w3p = pack2(wq.w);
            fma2(acc[0],  ya.x, w0p); fma2(acc[1],  ya.y, w0p);
            fma2(acc[2],  yb.x, w0p); fma2(acc[3],  yb.y, w0p);
            fma2(acc[4],  ya.x, w1p); fma2(acc[5],  ya.y, w1p);
            fma2(acc[6],  yb.x, w1p); fma2(acc[7],  yb.y, w1p);
            fma2(acc[8],  ya.x, w2p); fma2(acc[9],  ya.y, w2p);
            fma2(acc[10], yb.x, w2p); fma2(acc[11], yb.y, w2p);
            fma2(acc[12], ya.x, w3p); fma2(acc[13], ya.y, w3p);
            fma2(acc[14], yb.x, w3p); fma2(acc[15], yb.y, w3p);
        }
        // per-thread reduce over 8 k, then shuffle over kg (lane bits 0-1)
        float mx[4], mn[4];
        #pragma unroll
        for (int cl = 0; cl < 4; ++cl) {
            float mxv = -3.4e38f, mnv = 3.4e38f, sz = 0.f, sq = 0.f;
            #pragma unroll
            for (int kp = 0; kp < 4; ++kp) {
                float2 v = unpack2(acc[cl*4 + kp]);
                mxv = fmaxf(mxv, fmaxf(v.x, v.y));
                mnv = fminf(mnv, fminf(v.x, v.y));
                sz += v.x + v.y;
                sq = fmaf(v.x, v.x, fmaf(v.y, v.y, sq));
            }
            zs[cl] += sz; zq[cl] += sq;
            mxv = fmaxf(mxv, __shfl_xor_sync(0xffffffffu, mxv, 1));
            mxv = fmaxf(mxv, __shfl_xor_sync(0xffffffffu, mxv, 2));
            mnv = fminf(mnv, __shfl_xor_sync(0xffffffffu, mnv, 1));
            mnv = fminf(mnv, __shfl_xor_sync(0xffffffffu, mnv, 2));
            mx[cl] = mxv; mn[cl] = mnv;
        }
        if (kg == 0) {
            *(float4*)&g_mx[p*CC2 + cBase] = make_float4(mx[0], mx[1], mx[2], mx[3]);
            *(float4*)&g_mn[p*CC2 + cBase] = make_float4(mn[0], mn[1], mn[2], mn[3]);
        }
    }
    // BN2 partials: deterministic shuffle-reduce over kg, per-warp-owned channels
    #pragma unroll
    for (int cl = 0; cl < 4; ++cl) {
        float S = zs[cl], Q = zq[cl];
        S += __shfl_xor_sync(0xffffffffu, S, 1);
        S += __shfl_xor_sync(0xffffffffu, S, 2);
        Q += __shfl_xor_sync(0xffffffffu, Q, 1);
        Q += __shfl_xor_sync(0xffffffffu, Q, 2);
        if (kg == 0) {
            g_p2s[blockIdx.x][cBase + cl] = (double)S;
            g_p2q[blockIdx.x][cBase + cl] = (double)Q;
        }
    }
}

// ---------------- K3b: finalize BN2 (parallel over slots) ----------------
__global__ void k_fin2(const float* __restrict__ gm, const float* __restrict__ bt) {
    __shared__ double shs[1024], shq[1024];
    int t = threadIdx.x;               // 1024 threads: c = t&127, s = t>>7 (0..7)
    int c = t & 127, s = t >> 7;
    double S = 0.0, Q = 0.0;
    for (int b = s; b < NB2; b += 8) { S += g_p2s[b][c]; Q += g_p2q[b][c]; }
    shs[t] = S; shq[t] = Q;
    __syncthreads();
    if (t < 128) {
        S = 0.0; Q = 0.0;
        #pragma unroll
        for (int k = 0; k < 8; ++k) { S += shs[k*128 + t]; Q += shq[k*128 + t]; }
        double mean = S / (double)ROWS;
        double var  = Q / (double)ROWS - mean*mean;
        float a = gm[t] * rsqrtf((float)(var + EPSd));
        g_a2[t]  = a;
        g_b2c[t] = bt[t] - (float)mean * a;
    }
}

// ---------------- K4: epilogue ----------------
__global__ void k_out(float* __restrict__ out) {
    int idx = blockIdx.x*blockDim.x + threadIdx.x;
    if (idx >= NPTS*CC2) return;
    int c = idx & (CC2-1);
    float a = g_a2[c], b = g_b2c[c];
    float v = (a >= 0.f) ? g_mx[idx] : g_mn[idx];
    out[idx] = fmaxf(fmaf(a, v, b), 0.f);
}

// ---------------- launch ----------------
extern "C" void kernel_launch(void* const* d_in, const int* in_sizes, int n_in,
                              void* d_out, int out_size) {
    (void)in_sizes; (void)n_in; (void)out_size;
    const float* pos  = (const float*)d_in[0];
    const float* feat = (const float*)d_in[1];
    const float* W1   = (const float*)d_in[2];
    const float* g1   = (const float*)d_in[3];
    const float* b1   = (const float*)d_in[4];
    const float* W2   = (const float*)d_in[5];
    const float* g2   = (const float*)d_in[6];
    const float* b2   = (const float*)d_in[7];
    float* out = (float*)d_out;

    cudaMemcpyAsync(out, pos, (size_t)BB*NN*3*sizeof(float),
                    cudaMemcpyDeviceToDevice);

    k_ball  <<<BB*(NN/128), 128>>>(pos);
    k_f1    <<<NPTS/128, 128>>>(pos, feat, W1);
    k_stats1<<<NB1, 256>>>();
    k_fin1  <<<1, 512>>>(g1, b1);
    k_main  <<<NB2, 128>>>(W2);
    k_fin2  <<<1, 1024>>>(g2, b2);
    k_out   <<<(NPTS*CC2)/256, 256>>>(out + BB*NN*3);
}